// round 5
// baseline (speedup 1.0000x reference)
#include <cuda_runtime.h>
#include <cuda_bf16.h>
#include <cstdint>

#define NN   50000
#define EE   600000
#define FEAT 11
#define DD   128
#define BBATCH 500
#define MAXA 100
#define NLAYERS 5
#define DENSE (BBATCH*MAXA*DD)   /* 6,400,000 */

#define SCAN_BS   1024
#define SCAN_NB   ((NN + SCAN_BS - 1) / SCAN_BS)   /* 49 */

#define TILE_M    128
#define GEMM_NB   ((NN + TILE_M - 1) / TILE_M)     /* 391 */

// -------- scratch (static device globals; zero-initialized, no runtime alloc) --------
__device__ float g_x[NN*DD];              // fp32 ping (25.6 MB)
__device__ float g_x2[NN*DD];             // fp32 pong
__device__ __nv_bfloat16 g_wthi[NLAYERS*DD*DD]; // W transposed [l][n][k], bf16 hi
__device__ __nv_bfloat16 g_wtlo[NLAYERS*DD*DD]; // bf16 lo
__device__ float g_dinv[NN];
__device__ float g_self[NN];
__device__ int   g_deg[NN];
__device__ int   g_rowstart[NN+1];
__device__ int   g_cursor[NN];
__device__ int   g_csr_src[EE];
__device__ float g_csr_w[EE];
__device__ int   g_counts[BBATCH];
__device__ int   g_ptr[BBATCH];
__device__ int   g_bsum[SCAN_NB];
__device__ int   g_boff[SCAN_NB];

// ---------------- graph preprocessing ----------------
__global__ void k_zero()
{
    int i = blockIdx.x * blockDim.x + threadIdx.x;
    if (i < NN) g_deg[i] = 0;
    if (i < BBATCH) g_counts[i] = 0;
}

__global__ void k_hist(const int* __restrict__ col, const int* __restrict__ batch)
{
    int i = blockIdx.x * blockDim.x + threadIdx.x;
    if (i < EE) atomicAdd(&g_deg[col[i]], 1);
    if (i < NN) atomicAdd(&g_counts[batch[i]], 1);
}

__global__ void k_dinv()
{
    int i = blockIdx.x * blockDim.x + threadIdx.x;
    if (i >= NN) return;
    float d  = (float)g_deg[i] + 2.0f;
    float di = rsqrtf(d);
    g_dinv[i] = di;
    g_self[i] = 2.0f * di * di;
}

__global__ __launch_bounds__(SCAN_BS)
void k_scan1()
{
    __shared__ int warp_sums[32];
    int tid  = threadIdx.x;
    int lane = tid & 31;
    int wid  = tid >> 5;
    int i    = blockIdx.x * SCAN_BS + tid;

    int v0 = (i < NN) ? g_deg[i] : 0;
    int v  = v0;
    #pragma unroll
    for (int off = 1; off < 32; off <<= 1) {
        int t = __shfl_up_sync(0xffffffffu, v, off);
        if (lane >= off) v += t;
    }
    if (lane == 31) warp_sums[wid] = v;
    __syncthreads();
    if (wid == 0) {
        int s = warp_sums[lane];
        #pragma unroll
        for (int off = 1; off < 32; off <<= 1) {
            int t = __shfl_up_sync(0xffffffffu, s, off);
            if (lane >= off) s += t;
        }
        warp_sums[lane] = s;
    }
    __syncthreads();
    int incl = v + (wid ? warp_sums[wid-1] : 0);
    if (i < NN) {
        g_rowstart[i+1] = incl;
        g_cursor[i]     = incl - v0;
    }
    if (tid == SCAN_BS - 1) g_bsum[blockIdx.x] = incl;
}

__global__ __launch_bounds__(512)
void k_scan2()
{
    __shared__ int sb[64];
    __shared__ int warp_sums[16];
    int tid  = threadIdx.x;
    int lane = tid & 31;
    int wid  = tid >> 5;

    if (tid < 64) sb[tid] = (tid < SCAN_NB) ? g_bsum[tid] : 0;
    __syncthreads();
    #pragma unroll
    for (int off = 1; off < 64; off <<= 1) {
        int t = 0;
        if (tid < 64 && tid >= off) t = sb[tid - off];
        __syncthreads();
        if (tid < 64) sb[tid] += t;
        __syncthreads();
    }
    if (tid < SCAN_NB) g_boff[tid] = (tid == 0) ? 0 : sb[tid - 1];
    if (tid == 0) g_rowstart[0] = 0;

    int c = (tid < BBATCH) ? g_counts[tid] : 0;
    int v = c;
    #pragma unroll
    for (int off = 1; off < 32; off <<= 1) {
        int t = __shfl_up_sync(0xffffffffu, v, off);
        if (lane >= off) v += t;
    }
    if (lane == 31) warp_sums[wid] = v;
    __syncthreads();
    if (wid == 0 && lane < 16) {
        int s = warp_sums[lane];
        #pragma unroll
        for (int off = 1; off < 16; off <<= 1) {
            int t = __shfl_up_sync(0xffffu, s, off);
            if (lane >= off) s += t;
        }
        warp_sums[lane] = s;
    }
    __syncthreads();
    int incl = v + (wid ? warp_sums[wid-1] : 0);
    if (tid < BBATCH) g_ptr[tid] = incl - c;
}

__global__ __launch_bounds__(SCAN_BS)
void k_scan3()
{
    int i = blockIdx.x * SCAN_BS + threadIdx.x;
    if (i >= NN) return;
    int off = g_boff[blockIdx.x];
    g_rowstart[i+1] += off;
    g_cursor[i]     += off;
}

__global__ void k_csr(const int* __restrict__ conn)
{
    int e = blockIdx.x * blockDim.x + threadIdx.x;
    if (e >= EE) return;
    int r = conn[e];
    int c = conn[EE + e];
    int slot = atomicAdd(&g_cursor[c], 1);
    g_csr_src[slot] = r;
    g_csr_w[slot]   = g_dinv[r] * g_dinv[c];
}

// ---- transpose W to [l][n][k] and split into bf16 hi/lo ----
__global__ void k_prepw(const float* __restrict__ Ws)
{
    int idx = blockIdx.x * blockDim.x + threadIdx.x;
    if (idx >= NLAYERS*DD*DD) return;
    int l = idx >> 14;
    int r = idx & 16383;
    int n = r >> 7;
    int k = r & 127;
    float v = Ws[l*DD*DD + k*DD + n];
    __nv_bfloat16 hi = __float2bfloat16_rn(v);
    __nv_bfloat16 lo = __float2bfloat16_rn(v - __bfloat162float(hi));
    g_wthi[idx] = hi;
    g_wtlo[idx] = lo;
}

// ---------------- log-expansion: x0 = log(atoms+1) @ W_exp + b_exp ----------------
__global__ void k_expand(const float* __restrict__ atoms,
                         const float* __restrict__ Wexp,
                         const float* __restrict__ bexp)
{
    __shared__ float sW[FEAT*DD];
    __shared__ float sb[DD];
    __shared__ float la[FEAT];
    int tid = threadIdx.x;
    for (int i = tid; i < FEAT*DD; i += DD) sW[i] = Wexp[i];
    sb[tid] = bexp[tid];
    for (int n = blockIdx.x; n < NN; n += gridDim.x) {
        __syncthreads();
        if (tid < FEAT) la[tid] = logf(atoms[n*FEAT + tid] + 1.0f);
        __syncthreads();
        float acc = sb[tid];
        #pragma unroll
        for (int f = 0; f < FEAT; f++) acc = fmaf(la[f], sW[f*DD + tid], acc);
        g_x[n*DD + tid] = acc;
    }
}

// ================= fused layer: aggregate -> smem bf16 hi/lo -> mma -> epilogue ====
// smem word address for (row 0..127, word 0..63), XOR-swizzled at 16B granularity
__device__ __forceinline__ int sww(int row, int w) {
    return row*64 + ((((w >> 2) ^ (row & 7)) << 2) | (w & 3));
}

__device__ __forceinline__ void mma_bf16(float* d, const uint32_t* a, const uint32_t* b)
{
    asm volatile(
        "mma.sync.aligned.m16n8k16.row.col.f32.bf16.bf16.f32 "
        "{%0,%1,%2,%3}, {%4,%5,%6,%7}, {%8,%9}, {%0,%1,%2,%3};"
        : "+f"(d[0]), "+f"(d[1]), "+f"(d[2]), "+f"(d[3])
        : "r"(a[0]), "r"(a[1]), "r"(a[2]), "r"(a[3]), "r"(b[0]), "r"(b[1]));
}

#define LAYER_SMEM (2*128*64*4)   /* sHi + sLo = 64 KB */

template<bool LAST>
__global__ __launch_bounds__(256)
void k_layer(const float* __restrict__ x,
             const __nv_bfloat16* __restrict__ whi,
             const __nv_bfloat16* __restrict__ wlo,
             const float* __restrict__ bias,
             float* __restrict__ xout,
             const int* __restrict__ batch)
{
    extern __shared__ uint32_t smem[];
    uint32_t* sHi = smem;
    uint32_t* sLo = smem + 128*64;

    int tid  = threadIdx.x;
    int lane = tid & 31;
    int wid  = tid >> 5;
    int rowBase = blockIdx.x * TILE_M;

    // ---- phase 1: aggregation (warp per node, 16 nodes per warp) ----
    const float4* xr = reinterpret_cast<const float4*>(x);
    for (int i = 0; i < 16; i++) {
        int r = wid*16 + i;               // local row 0..127
        int m = rowBase + r;
        float4 acc = make_float4(0.f, 0.f, 0.f, 0.f);
        if (m < NN) {
            float4 a  = xr[m*32 + lane];
            float  sn = g_self[m];
            acc = make_float4(a.x*sn, a.y*sn, a.z*sn, a.w*sn);
            int s = g_rowstart[m];
            int e = g_rowstart[m+1];
            int j = s;
            for (; j + 4 <= e; j += 4) {
                int   s0 = g_csr_src[j],   s1 = g_csr_src[j+1];
                int   s2 = g_csr_src[j+2], s3 = g_csr_src[j+3];
                float w0 = g_csr_w[j],     w1 = g_csr_w[j+1];
                float w2 = g_csr_w[j+2],   w3 = g_csr_w[j+3];
                float4 u0 = xr[s0*32 + lane];
                float4 u1 = xr[s1*32 + lane];
                float4 u2 = xr[s2*32 + lane];
                float4 u3 = xr[s3*32 + lane];
                acc.x = fmaf(u0.x, w0, acc.x); acc.y = fmaf(u0.y, w0, acc.y);
                acc.z = fmaf(u0.z, w0, acc.z); acc.w = fmaf(u0.w, w0, acc.w);
                acc.x = fmaf(u1.x, w1, acc.x); acc.y = fmaf(u1.y, w1, acc.y);
                acc.z = fmaf(u1.z, w1, acc.z); acc.w = fmaf(u1.w, w1, acc.w);
                acc.x = fmaf(u2.x, w2, acc.x); acc.y = fmaf(u2.y, w2, acc.y);
                acc.z = fmaf(u2.z, w2, acc.z); acc.w = fmaf(u2.w, w2, acc.w);
                acc.x = fmaf(u3.x, w3, acc.x); acc.y = fmaf(u3.y, w3, acc.y);
                acc.z = fmaf(u3.z, w3, acc.z); acc.w = fmaf(u3.w, w3, acc.w);
            }
            for (; j < e; j++) {
                int   src = g_csr_src[j];
                float wt  = g_csr_w[j];
                float4 u  = xr[src*32 + lane];
                acc.x = fmaf(u.x, wt, acc.x);
                acc.y = fmaf(u.y, wt, acc.y);
                acc.z = fmaf(u.z, wt, acc.z);
                acc.w = fmaf(u.w, wt, acc.w);
            }
        }
        // split to bf16 hi/lo, pack, store swizzled (lane owns words lane*2, lane*2+1)
        float vv[4] = {acc.x, acc.y, acc.z, acc.w};
        uint32_t ph[2], pl[2];
        #pragma unroll
        for (int h = 0; h < 2; h++) {
            __nv_bfloat16 h0 = __float2bfloat16_rn(vv[h*2]);
            __nv_bfloat16 h1 = __float2bfloat16_rn(vv[h*2+1]);
            __nv_bfloat16 l0 = __float2bfloat16_rn(vv[h*2]   - __bfloat162float(h0));
            __nv_bfloat16 l1 = __float2bfloat16_rn(vv[h*2+1] - __bfloat162float(h1));
            ph[h] = ((uint32_t)__bfloat16_as_ushort(h1) << 16) | __bfloat16_as_ushort(h0);
            pl[h] = ((uint32_t)__bfloat16_as_ushort(l1) << 16) | __bfloat16_as_ushort(l0);
        }
        sHi[sww(r, lane*2)]     = ph[0];
        sHi[sww(r, lane*2 + 1)] = ph[1];
        sLo[sww(r, lane*2)]     = pl[0];
        sLo[sww(r, lane*2 + 1)] = pl[1];
    }
    __syncthreads();

    // ---- phase 2: 3-term bf16 MMA (A from smem, B from global) ----
    int warp_m = wid & 3;
    int warp_n = wid >> 2;
    int g      = lane >> 2;
    int tq     = lane & 3;
    int colBase = warp_n * 64;

    int r0 = warp_m*32 + g;
    int r1 = r0 + 8;
    int r2 = r0 + 16;
    int r3 = r0 + 24;

    const uint32_t* BH = reinterpret_cast<const uint32_t*>(whi);
    const uint32_t* BL = reinterpret_cast<const uint32_t*>(wlo);
    const uint32_t* bh = BH + (colBase + g) * 64;
    const uint32_t* bl = BL + (colBase + g) * 64;

    float d[2][8][4];
    #pragma unroll
    for (int mt = 0; mt < 2; mt++)
        #pragma unroll
        for (int nt = 0; nt < 8; nt++)
            #pragma unroll
            for (int q = 0; q < 4; q++) d[mt][nt][q] = 0.0f;

    #pragma unroll 4
    for (int ks = 0; ks < 8; ks++) {
        int o0 = ks*8 + tq;
        int o1 = o0 + 4;

        uint32_t aH[2][4], aL[2][4];
        aH[0][0] = sHi[sww(r0, o0)]; aH[0][1] = sHi[sww(r1, o0)];
        aH[0][2] = sHi[sww(r0, o1)]; aH[0][3] = sHi[sww(r1, o1)];
        aH[1][0] = sHi[sww(r2, o0)]; aH[1][1] = sHi[sww(r3, o0)];
        aH[1][2] = sHi[sww(r2, o1)]; aH[1][3] = sHi[sww(r3, o1)];
        aL[0][0] = sLo[sww(r0, o0)]; aL[0][1] = sLo[sww(r1, o0)];
        aL[0][2] = sLo[sww(r0, o1)]; aL[0][3] = sLo[sww(r1, o1)];
        aL[1][0] = sLo[sww(r2, o0)]; aL[1][1] = sLo[sww(r3, o0)];
        aL[1][2] = sLo[sww(r2, o1)]; aL[1][3] = sLo[sww(r3, o1)];

        uint32_t bHf[8][2];
        #pragma unroll
        for (int nt = 0; nt < 8; nt++) {
            bHf[nt][0] = bh[nt*512 + o0];
            bHf[nt][1] = bh[nt*512 + o1];
        }
        #pragma unroll
        for (int mt = 0; mt < 2; mt++)
            #pragma unroll
            for (int nt = 0; nt < 8; nt++)
                mma_bf16(d[mt][nt], aH[mt], bHf[nt]);
        #pragma unroll
        for (int mt = 0; mt < 2; mt++)
            #pragma unroll
            for (int nt = 0; nt < 8; nt++)
                mma_bf16(d[mt][nt], aL[mt], bHf[nt]);

        uint32_t bLf[8][2];
        #pragma unroll
        for (int nt = 0; nt < 8; nt++) {
            bLf[nt][0] = bl[nt*512 + o0];
            bLf[nt][1] = bl[nt*512 + o1];
        }
        #pragma unroll
        for (int mt = 0; mt < 2; mt++)
            #pragma unroll
            for (int nt = 0; nt < 8; nt++)
                mma_bf16(d[mt][nt], aH[mt], bLf[nt]);
    }

    // ---- epilogue: bias + relu; write next-x or scatter to dense output ----
    #pragma unroll
    for (int mt = 0; mt < 2; mt++) {
        int m0 = rowBase + warp_m*32 + mt*16 + g;
        int m1 = m0 + 8;
        int or0 = -1, or1 = -1;
        if (LAST) {
            if (m0 < NN) { int b = batch[m0]; or0 = b*MAXA + (m0 - g_ptr[b]); }
            if (m1 < NN) { int b = batch[m1]; or1 = b*MAXA + (m1 - g_ptr[b]); }
        } else {
            or0 = m0; or1 = m1;
        }
        #pragma unroll
        for (int nt = 0; nt < 8; nt++) {
            int cn = colBase + nt*8 + tq*2;
            float2 bv = *reinterpret_cast<const float2*>(bias + cn);
            if (m0 < NN) {
                float2 o;
                o.x = fmaxf(d[mt][nt][0] + bv.x, 0.f);
                o.y = fmaxf(d[mt][nt][1] + bv.y, 0.f);
                *reinterpret_cast<float2*>(xout + or0*DD + cn) = o;
            }
            if (m1 < NN) {
                float2 o;
                o.x = fmaxf(d[mt][nt][2] + bv.x, 0.f);
                o.y = fmaxf(d[mt][nt][3] + bv.y, 0.f);
                *reinterpret_cast<float2*>(xout + or1*DD + cn) = o;
            }
        }
    }
}

// ---------------- output helpers ----------------
__global__ void k_zero_out(float* __restrict__ out, int n)
{
    int i = blockIdx.x * blockDim.x + threadIdx.x;
    if (i < n) out[i] = 0.0f;
}

__global__ void k_mask(const int* __restrict__ batch, float* __restrict__ out, int out_size)
{
    int i = blockIdx.x * blockDim.x + threadIdx.x;
    if (i >= NN) return;
    if (out_size >= DENSE + BBATCH*MAXA) {
        int b = batch[i];
        out[DENSE + b*MAXA + (i - g_ptr[b])] = 1.0f;
    }
}

// ---------------- launch ----------------
extern "C" void kernel_launch(void* const* d_in, const int* in_sizes, int n_in,
                              void* d_out, int out_size)
{
    const float* atoms = (const float*)d_in[0];
    const int*   conn  = (const int*)d_in[1];
    const int*   batch = (const int*)d_in[2];
    const float* W_exp = (const float*)d_in[3];
    const float* b_exp = (const float*)d_in[4];
    const float* Ws    = (const float*)d_in[5];
    const float* bs    = (const float*)d_in[6];
    float* out = (float*)d_out;

    float *px, *px2;
    __nv_bfloat16 *pwhi, *pwlo;
    cudaGetSymbolAddress((void**)&px,   g_x);
    cudaGetSymbolAddress((void**)&px2,  g_x2);
    cudaGetSymbolAddress((void**)&pwhi, g_wthi);
    cudaGetSymbolAddress((void**)&pwlo, g_wtlo);

    cudaFuncSetAttribute(k_layer<false>, cudaFuncAttributeMaxDynamicSharedMemorySize, LAYER_SMEM);
    cudaFuncSetAttribute(k_layer<true>,  cudaFuncAttributeMaxDynamicSharedMemorySize, LAYER_SMEM);

    k_zero<<<(NN + 255)/256, 256>>>();
    k_hist<<<(EE + 255)/256, 256>>>(conn + EE, batch);
    k_dinv<<<(NN + 255)/256, 256>>>();
    k_scan1<<<SCAN_NB, SCAN_BS>>>();
    k_scan2<<<1, 512>>>();
    k_scan3<<<SCAN_NB, SCAN_BS>>>();
    k_csr<<<(EE + 255)/256, 256>>>(conn);
    k_prepw<<<(NLAYERS*DD*DD + 255)/256, 256>>>(Ws);
    k_expand<<<4096, DD>>>(atoms, W_exp, b_exp);
    k_zero_out<<<(out_size + 255)/256, 256>>>(out, out_size);

    // layers 0..3: ping-pong x; layer 4: scatter straight into dense output
    k_layer<false><<<GEMM_NB, 256, LAYER_SMEM>>>(px,  pwhi + 0*DD*DD, pwlo + 0*DD*DD, bs + 0*DD, px2, batch);
    k_layer<false><<<GEMM_NB, 256, LAYER_SMEM>>>(px2, pwhi + 1*DD*DD, pwlo + 1*DD*DD, bs + 1*DD, px,  batch);
    k_layer<false><<<GEMM_NB, 256, LAYER_SMEM>>>(px,  pwhi + 2*DD*DD, pwlo + 2*DD*DD, bs + 2*DD, px2, batch);
    k_layer<false><<<GEMM_NB, 256, LAYER_SMEM>>>(px2, pwhi + 3*DD*DD, pwlo + 3*DD*DD, bs + 3*DD, px,  batch);
    k_layer<true> <<<GEMM_NB, 256, LAYER_SMEM>>>(px,  pwhi + 4*DD*DD, pwlo + 4*DD*DD, bs + 4*DD, out, batch);

    k_mask<<<(NN + 255)/256, 256>>>(batch, out, out_size);
}

// round 6
// speedup vs baseline: 1.5343x; 1.5343x over previous
#include <cuda_runtime.h>
#include <cuda_bf16.h>
#include <cstdint>

#define NN   50000
#define EE   600000
#define FEAT 11
#define DD   128
#define BBATCH 500
#define MAXA 100
#define NLAYERS 5
#define DENSE (BBATCH*MAXA*DD)   /* 6,400,000 */

#define SCAN_BS   1024
#define SCAN_NB   ((NN + SCAN_BS - 1) / SCAN_BS)   /* 49 */

#define TILE_M    128
#define GEMM_NB   ((NN + TILE_M - 1) / TILE_M)     /* 391 */
#define NNP       (GEMM_NB * TILE_M)               /* 50048, padded */

// -------- scratch (static device globals; zero-initialized, no runtime alloc) --------
__device__ float g_x[NN*DD];              // fp32 ping (25.6 MB)
__device__ __nv_bfloat16 g_ahi[NNP*DD];   // agg result, bf16 hi (pad rows stay 0 forever)
__device__ __nv_bfloat16 g_alo[NNP*DD];   // agg result, bf16 lo
__device__ __nv_bfloat16 g_wthi[NLAYERS*DD*DD]; // W transposed [l][n][k], bf16 hi
__device__ __nv_bfloat16 g_wtlo[NLAYERS*DD*DD]; // bf16 lo
__device__ float g_dinv[NN];
__device__ float g_self[NN];
__device__ int   g_deg[NN];
__device__ int   g_rowstart[NN+1];
__device__ int   g_cursor[NN];
__device__ int   g_csr_src[EE];
__device__ float g_csr_w[EE];
__device__ int   g_counts[BBATCH];
__device__ int   g_ptr[BBATCH];
__device__ int   g_bsum[SCAN_NB];
__device__ int   g_boff[SCAN_NB];

// ---------------- graph preprocessing ----------------
__global__ void k_zero()
{
    int i = blockIdx.x * blockDim.x + threadIdx.x;
    if (i < NN) g_deg[i] = 0;
    if (i < BBATCH) g_counts[i] = 0;
}

__global__ void k_hist(const int* __restrict__ col, const int* __restrict__ batch)
{
    int i = blockIdx.x * blockDim.x + threadIdx.x;
    if (i < EE) atomicAdd(&g_deg[col[i]], 1);
    if (i < NN) atomicAdd(&g_counts[batch[i]], 1);
}

// scan1 also computes dinv/self (deg value already in hand)
__global__ __launch_bounds__(SCAN_BS)
void k_scan1()
{
    __shared__ int warp_sums[32];
    int tid  = threadIdx.x;
    int lane = tid & 31;
    int wid  = tid >> 5;
    int i    = blockIdx.x * SCAN_BS + tid;

    int v0 = (i < NN) ? g_deg[i] : 0;
    if (i < NN) {
        float d  = (float)v0 + 2.0f;
        float di = rsqrtf(d);
        g_dinv[i] = di;
        g_self[i] = 2.0f * di * di;
    }
    int v  = v0;
    #pragma unroll
    for (int off = 1; off < 32; off <<= 1) {
        int t = __shfl_up_sync(0xffffffffu, v, off);
        if (lane >= off) v += t;
    }
    if (lane == 31) warp_sums[wid] = v;
    __syncthreads();
    if (wid == 0) {
        int s = warp_sums[lane];
        #pragma unroll
        for (int off = 1; off < 32; off <<= 1) {
            int t = __shfl_up_sync(0xffffffffu, s, off);
            if (lane >= off) s += t;
        }
        warp_sums[lane] = s;
    }
    __syncthreads();
    int incl = v + (wid ? warp_sums[wid-1] : 0);
    if (i < NN) {
        g_rowstart[i+1] = incl;
        g_cursor[i]     = incl - v0;
    }
    if (tid == SCAN_BS - 1) g_bsum[blockIdx.x] = incl;
}

__global__ __launch_bounds__(512)
void k_scan2()
{
    __shared__ int sb[64];
    __shared__ int warp_sums[16];
    int tid  = threadIdx.x;
    int lane = tid & 31;
    int wid  = tid >> 5;

    if (tid < 64) sb[tid] = (tid < SCAN_NB) ? g_bsum[tid] : 0;
    __syncthreads();
    #pragma unroll
    for (int off = 1; off < 64; off <<= 1) {
        int t = 0;
        if (tid < 64 && tid >= off) t = sb[tid - off];
        __syncthreads();
        if (tid < 64) sb[tid] += t;
        __syncthreads();
    }
    if (tid < SCAN_NB) g_boff[tid] = (tid == 0) ? 0 : sb[tid - 1];
    if (tid == 0) g_rowstart[0] = 0;

    int c = (tid < BBATCH) ? g_counts[tid] : 0;
    int v = c;
    #pragma unroll
    for (int off = 1; off < 32; off <<= 1) {
        int t = __shfl_up_sync(0xffffffffu, v, off);
        if (lane >= off) v += t;
    }
    if (lane == 31) warp_sums[wid] = v;
    __syncthreads();
    if (wid == 0 && lane < 16) {
        int s = warp_sums[lane];
        #pragma unroll
        for (int off = 1; off < 16; off <<= 1) {
            int t = __shfl_up_sync(0xffffu, s, off);
            if (lane >= off) s += t;
        }
        warp_sums[lane] = s;
    }
    __syncthreads();
    int incl = v + (wid ? warp_sums[wid-1] : 0);
    if (tid < BBATCH) g_ptr[tid] = incl - c;
}

__global__ __launch_bounds__(SCAN_BS)
void k_scan3()
{
    int i = blockIdx.x * SCAN_BS + threadIdx.x;
    if (i >= NN) return;
    int off = g_boff[blockIdx.x];
    g_rowstart[i+1] += off;
    g_cursor[i]     += off;
}

__global__ void k_csr(const int* __restrict__ conn)
{
    int e = blockIdx.x * blockDim.x + threadIdx.x;
    if (e >= EE) return;
    int r = conn[e];
    int c = conn[EE + e];
    int slot = atomicAdd(&g_cursor[c], 1);
    g_csr_src[slot] = r;
    g_csr_w[slot]   = g_dinv[r] * g_dinv[c];
}

// ---- transpose W to [l][n][k] and split into bf16 hi/lo ----
__global__ void k_prepw(const float* __restrict__ Ws)
{
    int idx = blockIdx.x * blockDim.x + threadIdx.x;
    if (idx >= NLAYERS*DD*DD) return;
    int l = idx >> 14;
    int r = idx & 16383;
    int n = r >> 7;
    int k = r & 127;
    float v = Ws[l*DD*DD + k*DD + n];
    __nv_bfloat16 hi = __float2bfloat16_rn(v);
    __nv_bfloat16 lo = __float2bfloat16_rn(v - __bfloat162float(hi));
    g_wthi[idx] = hi;
    g_wtlo[idx] = lo;
}

// ---------------- log-expansion: x0 = log(atoms+1) @ W_exp + b_exp ----------------
__global__ void k_expand(const float* __restrict__ atoms,
                         const float* __restrict__ Wexp,
                         const float* __restrict__ bexp)
{
    __shared__ float sW[FEAT*DD];
    __shared__ float sb[DD];
    __shared__ float la[FEAT];
    int tid = threadIdx.x;
    for (int i = tid; i < FEAT*DD; i += DD) sW[i] = Wexp[i];
    sb[tid] = bexp[tid];
    for (int n = blockIdx.x; n < NN; n += gridDim.x) {
        __syncthreads();
        if (tid < FEAT) la[tid] = logf(atoms[n*FEAT + tid] + 1.0f);
        __syncthreads();
        float acc = sb[tid];
        #pragma unroll
        for (int f = 0; f < FEAT; f++) acc = fmaf(la[f], sW[f*DD + tid], acc);
        g_x[n*DD + tid] = acc;
    }
}

// ---------------- per-layer aggregation: agg = Â x, emitted as bf16 hi/lo ----------------
__global__ void k_agg(const float* __restrict__ x)
{
    int w = (blockIdx.x * blockDim.x + threadIdx.x) >> 5;
    if (w >= NN) return;
    int lane = threadIdx.x & 31;
    const float4* xr = reinterpret_cast<const float4*>(x);

    float4 a  = xr[w*32 + lane];
    float  sn = g_self[w];
    float4 acc = make_float4(a.x*sn, a.y*sn, a.z*sn, a.w*sn);

    int s = g_rowstart[w];
    int e = g_rowstart[w+1];
    int j = s;
    for (; j + 4 <= e; j += 4) {
        int   s0 = g_csr_src[j],   s1 = g_csr_src[j+1];
        int   s2 = g_csr_src[j+2], s3 = g_csr_src[j+3];
        float w0 = g_csr_w[j],     w1 = g_csr_w[j+1];
        float w2 = g_csr_w[j+2],   w3 = g_csr_w[j+3];
        float4 u0 = xr[s0*32 + lane];
        float4 u1 = xr[s1*32 + lane];
        float4 u2 = xr[s2*32 + lane];
        float4 u3 = xr[s3*32 + lane];
        acc.x = fmaf(u0.x, w0, acc.x); acc.y = fmaf(u0.y, w0, acc.y);
        acc.z = fmaf(u0.z, w0, acc.z); acc.w = fmaf(u0.w, w0, acc.w);
        acc.x = fmaf(u1.x, w1, acc.x); acc.y = fmaf(u1.y, w1, acc.y);
        acc.z = fmaf(u1.z, w1, acc.z); acc.w = fmaf(u1.w, w1, acc.w);
        acc.x = fmaf(u2.x, w2, acc.x); acc.y = fmaf(u2.y, w2, acc.y);
        acc.z = fmaf(u2.z, w2, acc.z); acc.w = fmaf(u2.w, w2, acc.w);
        acc.x = fmaf(u3.x, w3, acc.x); acc.y = fmaf(u3.y, w3, acc.y);
        acc.z = fmaf(u3.z, w3, acc.z); acc.w = fmaf(u3.w, w3, acc.w);
    }
    for (; j < e; j++) {
        int   src = g_csr_src[j];
        float wt  = g_csr_w[j];
        float4 u  = xr[src*32 + lane];
        acc.x = fmaf(u.x, wt, acc.x);
        acc.y = fmaf(u.y, wt, acc.y);
        acc.z = fmaf(u.z, wt, acc.z);
        acc.w = fmaf(u.w, wt, acc.w);
    }

    float vv[4] = {acc.x, acc.y, acc.z, acc.w};
    __nv_bfloat16 hi[4], lo[4];
    #pragma unroll
    for (int q = 0; q < 4; q++) {
        hi[q] = __float2bfloat16_rn(vv[q]);
        lo[q] = __float2bfloat16_rn(vv[q] - __bfloat162float(hi[q]));
    }
    uint2 phi, plo;
    phi.x = ((uint32_t)__bfloat16_as_ushort(hi[1]) << 16) | __bfloat16_as_ushort(hi[0]);
    phi.y = ((uint32_t)__bfloat16_as_ushort(hi[3]) << 16) | __bfloat16_as_ushort(hi[2]);
    plo.x = ((uint32_t)__bfloat16_as_ushort(lo[1]) << 16) | __bfloat16_as_ushort(lo[0]);
    plo.y = ((uint32_t)__bfloat16_as_ushort(lo[3]) << 16) | __bfloat16_as_ushort(lo[2]);
    reinterpret_cast<uint2*>(g_ahi)[w*32 + lane] = phi;
    reinterpret_cast<uint2*>(g_alo)[w*32 + lane] = plo;
}

// ---------------- bf16 mma.sync GEMM: out = relu((Ahi+Alo)(Whi+Wlo)^T + b) ----------------
__device__ __forceinline__ void mma_bf16(float* d, const uint32_t* a, const uint32_t* b)
{
    asm volatile(
        "mma.sync.aligned.m16n8k16.row.col.f32.bf16.bf16.f32 "
        "{%0,%1,%2,%3}, {%4,%5,%6,%7}, {%8,%9}, {%0,%1,%2,%3};"
        : "+f"(d[0]), "+f"(d[1]), "+f"(d[2]), "+f"(d[3])
        : "r"(a[0]), "r"(a[1]), "r"(a[2]), "r"(a[3]), "r"(b[0]), "r"(b[1]));
}

template<bool LAST>
__global__ __launch_bounds__(256)
void k_gemm_mma(const __nv_bfloat16* __restrict__ ahi,
                const __nv_bfloat16* __restrict__ alo,
                const __nv_bfloat16* __restrict__ whi,
                const __nv_bfloat16* __restrict__ wlo,
                const float* __restrict__ bias,
                float* __restrict__ out,
                const int* __restrict__ batch)
{
    int tid    = threadIdx.x;
    int lane   = tid & 31;
    int wid    = tid >> 5;
    int warp_m = wid & 3;        // 0..3
    int warp_n = wid >> 2;       // 0..1
    int g      = lane >> 2;      // groupID 0..7
    int tq     = lane & 3;       // quad lane 0..3

    int rowBase = blockIdx.x * TILE_M + warp_m * 32;   // < NNP always
    int colBase = warp_n * 64;

    const uint32_t* AH = reinterpret_cast<const uint32_t*>(ahi);
    const uint32_t* AL = reinterpret_cast<const uint32_t*>(alo);
    const uint32_t* BH = reinterpret_cast<const uint32_t*>(whi);
    const uint32_t* BL = reinterpret_cast<const uint32_t*>(wlo);

    const uint32_t* ah0 = AH + (rowBase + g     ) * 64;
    const uint32_t* ah1 = AH + (rowBase + g +  8) * 64;
    const uint32_t* ah2 = AH + (rowBase + g + 16) * 64;
    const uint32_t* ah3 = AH + (rowBase + g + 24) * 64;
    const uint32_t* al0 = AL + (rowBase + g     ) * 64;
    const uint32_t* al1 = AL + (rowBase + g +  8) * 64;
    const uint32_t* al2 = AL + (rowBase + g + 16) * 64;
    const uint32_t* al3 = AL + (rowBase + g + 24) * 64;
    const uint32_t* bh  = BH + (colBase + g) * 64;
    const uint32_t* bl  = BL + (colBase + g) * 64;

    float d[2][8][4];
    #pragma unroll
    for (int mt = 0; mt < 2; mt++)
        #pragma unroll
        for (int nt = 0; nt < 8; nt++)
            #pragma unroll
            for (int q = 0; q < 4; q++) d[mt][nt][q] = 0.0f;

    #pragma unroll 4
    for (int ks = 0; ks < 8; ks++) {
        int o0 = ks*8 + tq;
        int o1 = o0 + 4;

        uint32_t aH[2][4], aL[2][4];
        aH[0][0] = ah0[o0]; aH[0][1] = ah1[o0]; aH[0][2] = ah0[o1]; aH[0][3] = ah1[o1];
        aH[1][0] = ah2[o0]; aH[1][1] = ah3[o0]; aH[1][2] = ah2[o1]; aH[1][3] = ah3[o1];
        aL[0][0] = al0[o0]; aL[0][1] = al1[o0]; aL[0][2] = al0[o1]; aL[0][3] = al1[o1];
        aL[1][0] = al2[o0]; aL[1][1] = al3[o0]; aL[1][2] = al2[o1]; aL[1][3] = al3[o1];

        uint32_t bHf[8][2];
        #pragma unroll
        for (int nt = 0; nt < 8; nt++) {
            bHf[nt][0] = bh[nt*512 + o0];
            bHf[nt][1] = bh[nt*512 + o1];
        }
        #pragma unroll
        for (int mt = 0; mt < 2; mt++)
            #pragma unroll
            for (int nt = 0; nt < 8; nt++)
                mma_bf16(d[mt][nt], aH[mt], bHf[nt]);
        #pragma unroll
        for (int mt = 0; mt < 2; mt++)
            #pragma unroll
            for (int nt = 0; nt < 8; nt++)
                mma_bf16(d[mt][nt], aL[mt], bHf[nt]);

        uint32_t bLf[8][2];
        #pragma unroll
        for (int nt = 0; nt < 8; nt++) {
            bLf[nt][0] = bl[nt*512 + o0];
            bLf[nt][1] = bl[nt*512 + o1];
        }
        #pragma unroll
        for (int mt = 0; mt < 2; mt++)
            #pragma unroll
            for (int nt = 0; nt < 8; nt++)
                mma_bf16(d[mt][nt], aH[mt], bLf[nt]);
    }

    // epilogue: bias + relu; LAST scatters into dense output
    #pragma unroll
    for (int mt = 0; mt < 2; mt++) {
        int m0 = rowBase + mt*16 + g;
        int m1 = m0 + 8;
        int or0 = m0, or1 = m1;
        if (LAST) {
            if (m0 < NN) { int b = batch[m0]; or0 = b*MAXA + (m0 - g_ptr[b]); }
            if (m1 < NN) { int b = batch[m1]; or1 = b*MAXA + (m1 - g_ptr[b]); }
        }
        #pragma unroll
        for (int nt = 0; nt < 8; nt++) {
            int cn = colBase + nt*8 + tq*2;
            float2 bv = *reinterpret_cast<const float2*>(bias + cn);
            if (m0 < NN) {
                float2 o;
                o.x = fmaxf(d[mt][nt][0] + bv.x, 0.f);
                o.y = fmaxf(d[mt][nt][1] + bv.y, 0.f);
                *reinterpret_cast<float2*>(out + or0*DD + cn) = o;
            }
            if (m1 < NN) {
                float2 o;
                o.x = fmaxf(d[mt][nt][2] + bv.x, 0.f);
                o.y = fmaxf(d[mt][nt][3] + bv.y, 0.f);
                *reinterpret_cast<float2*>(out + or1*DD + cn) = o;
            }
        }
    }
}

// ---------------- output helpers ----------------
__global__ void k_zero_out(float* __restrict__ out, int n)
{
    int i = blockIdx.x * blockDim.x + threadIdx.x;
    if (i < n) out[i] = 0.0f;
}

__global__ void k_mask(const int* __restrict__ batch, float* __restrict__ out, int out_size)
{
    int i = blockIdx.x * blockDim.x + threadIdx.x;
    if (i >= NN) return;
    if (out_size >= DENSE + BBATCH*MAXA) {
        int b = batch[i];
        out[DENSE + b*MAXA + (i - g_ptr[b])] = 1.0f;
    }
}

// ---------------- launch ----------------
extern "C" void kernel_launch(void* const* d_in, const int* in_sizes, int n_in,
                              void* d_out, int out_size)
{
    const float* atoms = (const float*)d_in[0];
    const int*   conn  = (const int*)d_in[1];
    const int*   batch = (const int*)d_in[2];
    const float* W_exp = (const float*)d_in[3];
    const float* b_exp = (const float*)d_in[4];
    const float* Ws    = (const float*)d_in[5];
    const float* bs    = (const float*)d_in[6];
    float* out = (float*)d_out;

    float *px;
    __nv_bfloat16 *pahi, *palo, *pwhi, *pwlo;
    cudaGetSymbolAddress((void**)&px,   g_x);
    cudaGetSymbolAddress((void**)&pahi, g_ahi);
    cudaGetSymbolAddress((void**)&palo, g_alo);
    cudaGetSymbolAddress((void**)&pwhi, g_wthi);
    cudaGetSymbolAddress((void**)&pwlo, g_wtlo);

    k_zero<<<(NN + 255)/256, 256>>>();
    k_hist<<<(EE + 255)/256, 256>>>(conn + EE, batch);
    k_scan1<<<SCAN_NB, SCAN_BS>>>();
    k_scan2<<<1, 512>>>();
    k_scan3<<<SCAN_NB, SCAN_BS>>>();
    k_csr<<<(EE + 255)/256, 256>>>(conn);
    k_prepw<<<(NLAYERS*DD*DD + 255)/256, 256>>>(Ws);
    k_expand<<<4096, DD>>>(atoms, W_exp, b_exp);
    k_zero_out<<<(out_size + 255)/256, 256>>>(out, out_size);

    int aggBlocks = (NN*32 + 255)/256;
    for (int l = 0; l < NLAYERS - 1; l++) {
        k_agg<<<aggBlocks, 256>>>(px);
        k_gemm_mma<false><<<GEMM_NB, 256>>>(pahi, palo, pwhi + l*DD*DD, pwlo + l*DD*DD,
                                            bs + l*DD, px, batch);
    }
    // last layer: GEMM scatters directly into dense output
    k_agg<<<aggBlocks, 256>>>(px);
    k_gemm_mma<true><<<GEMM_NB, 256>>>(pahi, palo, pwhi + 4*DD*DD, pwlo + 4*DD*DD,
                                       bs + 4*DD, out, batch);

    k_mask<<<(NN + 255)/256, 256>>>(batch, out, out_size);
}

// round 7
// speedup vs baseline: 2.0035x; 1.3058x over previous
#include <cuda_runtime.h>
#include <cuda_bf16.h>
#include <cstdint>

#define NN   50000
#define EE   600000
#define FEAT 11
#define DD   128
#define BBATCH 500
#define MAXA 100
#define NLAYERS 5
#define DENSE (BBATCH*MAXA*DD)   /* 6,400,000 */
#define MASKN (BBATCH*MAXA)      /* 50,000 */

#define SCAN_BS   1024
#define SCAN_NB   ((NN + SCAN_BS - 1) / SCAN_BS)   /* 49 */

#define TILE_M    128
#define GEMM_NB   ((NN + TILE_M - 1) / TILE_M)     /* 391 */
#define NNP       (GEMM_NB * TILE_M)               /* 50048, padded */

// -------- scratch (static device globals; zero-initialized, no runtime alloc) --------
__device__ float g_x[NN*DD];                       // fp32 ping (25.6 MB)
__device__ __nv_bfloat16 g_apk[NNP*DD*2];          // packed agg: per word-pair {hi0,hi1,lo0,lo1}
__device__ __nv_bfloat16 g_wpk[NLAYERS*DD*DD*2];   // packed Wt [l][n]: same interleave
__device__ float g_dinv[NN];
__device__ float g_self[NN];
__device__ int   g_deg[NN];
__device__ int   g_rowstart[NN+1];
__device__ int   g_cursor[NN];
__device__ int   g_csr_src[EE];
__device__ float g_csr_w[EE];
__device__ int   g_counts[BBATCH];
__device__ int   g_ptr[BBATCH];
__device__ int   g_bsum[SCAN_NB];
__device__ int   g_boff[SCAN_NB];

// ---------------- graph preprocessing ----------------
__global__ void k_zero()
{
    int i = blockIdx.x * blockDim.x + threadIdx.x;
    if (i < NN) g_deg[i] = 0;
    if (i < BBATCH) g_counts[i] = 0;
}

__global__ void k_hist(const int* __restrict__ col, const int* __restrict__ batch)
{
    int i = blockIdx.x * blockDim.x + threadIdx.x;
    if (i < EE) atomicAdd(&g_deg[col[i]], 1);
    if (i < NN) atomicAdd(&g_counts[batch[i]], 1);
}

// scan1 also computes dinv/self (deg value already in hand)
__global__ __launch_bounds__(SCAN_BS)
void k_scan1()
{
    __shared__ int warp_sums[32];
    int tid  = threadIdx.x;
    int lane = tid & 31;
    int wid  = tid >> 5;
    int i    = blockIdx.x * SCAN_BS + tid;

    int v0 = (i < NN) ? g_deg[i] : 0;
    if (i < NN) {
        float d  = (float)v0 + 2.0f;
        float di = rsqrtf(d);
        g_dinv[i] = di;
        g_self[i] = 2.0f * di * di;
    }
    int v  = v0;
    #pragma unroll
    for (int off = 1; off < 32; off <<= 1) {
        int t = __shfl_up_sync(0xffffffffu, v, off);
        if (lane >= off) v += t;
    }
    if (lane == 31) warp_sums[wid] = v;
    __syncthreads();
    if (wid == 0) {
        int s = warp_sums[lane];
        #pragma unroll
        for (int off = 1; off < 32; off <<= 1) {
            int t = __shfl_up_sync(0xffffffffu, s, off);
            if (lane >= off) s += t;
        }
        warp_sums[lane] = s;
    }
    __syncthreads();
    int incl = v + (wid ? warp_sums[wid-1] : 0);
    if (i < NN) {
        g_rowstart[i+1] = incl;
        g_cursor[i]     = incl - v0;
    }
    if (tid == SCAN_BS - 1) g_bsum[blockIdx.x] = incl;
}

__global__ __launch_bounds__(512)
void k_scan2()
{
    __shared__ int sb[64];
    __shared__ int warp_sums[16];
    int tid  = threadIdx.x;
    int lane = tid & 31;
    int wid  = tid >> 5;

    if (tid < 64) sb[tid] = (tid < SCAN_NB) ? g_bsum[tid] : 0;
    __syncthreads();
    #pragma unroll
    for (int off = 1; off < 64; off <<= 1) {
        int t = 0;
        if (tid < 64 && tid >= off) t = sb[tid - off];
        __syncthreads();
        if (tid < 64) sb[tid] += t;
        __syncthreads();
    }
    if (tid < SCAN_NB) g_boff[tid] = (tid == 0) ? 0 : sb[tid - 1];
    if (tid == 0) g_rowstart[0] = 0;

    int c = (tid < BBATCH) ? g_counts[tid] : 0;
    int v = c;
    #pragma unroll
    for (int off = 1; off < 32; off <<= 1) {
        int t = __shfl_up_sync(0xffffffffu, v, off);
        if (lane >= off) v += t;
    }
    if (lane == 31) warp_sums[wid] = v;
    __syncthreads();
    if (wid == 0 && lane < 16) {
        int s = warp_sums[lane];
        #pragma unroll
        for (int off = 1; off < 16; off <<= 1) {
            int t = __shfl_up_sync(0xffffu, s, off);
            if (lane >= off) s += t;
        }
        warp_sums[lane] = s;
    }
    __syncthreads();
    int incl = v + (wid ? warp_sums[wid-1] : 0);
    if (tid < BBATCH) g_ptr[tid] = incl - c;
}

__global__ __launch_bounds__(SCAN_BS)
void k_scan3()
{
    int i = blockIdx.x * SCAN_BS + threadIdx.x;
    if (i >= NN) return;
    int off = g_boff[blockIdx.x];
    g_rowstart[i+1] += off;
    g_cursor[i]     += off;
}

// csr build + mask write (g_ptr ready; mask region untouched afterwards)
__global__ void k_csr(const int* __restrict__ conn, const int* __restrict__ batch,
                      float* __restrict__ out, int out_size)
{
    int e = blockIdx.x * blockDim.x + threadIdx.x;
    if (e < NN && out_size >= DENSE + MASKN) {
        int b = batch[e];
        out[DENSE + b*MAXA + (e - g_ptr[b])] = 1.0f;
    }
    if (e >= EE) return;
    int r = conn[e];
    int c = conn[EE + e];
    int slot = atomicAdd(&g_cursor[c], 1);
    g_csr_src[slot] = r;
    g_csr_w[slot]   = g_dinv[r] * g_dinv[c];
}

// ---- transpose W to [l][n][k], split bf16 hi/lo, interleave per word-pair ----
// layout per row n (256 bf16): word-pair j: [j*4+0]=hi(2j) [j*4+1]=hi(2j+1) [j*4+2]=lo(2j) [j*4+3]=lo(2j+1)
__global__ void k_prepw(const float* __restrict__ Ws)
{
    int idx = blockIdx.x * blockDim.x + threadIdx.x;
    if (idx >= NLAYERS*DD*DD) return;
    int l = idx >> 14;
    int r = idx & 16383;
    int n = r >> 7;
    int k = r & 127;
    float v = Ws[l*DD*DD + k*DD + n];
    __nv_bfloat16 hi = __float2bfloat16_rn(v);
    __nv_bfloat16 lo = __float2bfloat16_rn(v - __bfloat162float(hi));
    int base = (l*DD + n) * 256 + (k >> 1) * 4 + (k & 1);
    g_wpk[base]     = hi;
    g_wpk[base + 2] = lo;
}

// ---------------- log-expansion: x0 = log(atoms+1) @ W_exp + b_exp ----------------
__global__ void k_expand(const float* __restrict__ atoms,
                         const float* __restrict__ Wexp,
                         const float* __restrict__ bexp)
{
    __shared__ float sW[FEAT*DD];
    __shared__ float sb[DD];
    __shared__ float la[FEAT];
    int tid = threadIdx.x;
    for (int i = tid; i < FEAT*DD; i += DD) sW[i] = Wexp[i];
    sb[tid] = bexp[tid];
    for (int n = blockIdx.x; n < NN; n += gridDim.x) {
        __syncthreads();
        if (tid < FEAT) la[tid] = logf(atoms[n*FEAT + tid] + 1.0f);
        __syncthreads();
        float acc = sb[tid];
        #pragma unroll
        for (int f = 0; f < FEAT; f++) acc = fmaf(la[f], sW[f*DD + tid], acc);
        g_x[n*DD + tid] = acc;
    }
}

// ---------------- per-layer aggregation: agg = Â x, emitted packed bf16 hi/lo ----------------
__global__ void k_agg(const float* __restrict__ x)
{
    int w = (blockIdx.x * blockDim.x + threadIdx.x) >> 5;
    if (w >= NN) return;
    int lane = threadIdx.x & 31;
    const float4* xr = reinterpret_cast<const float4*>(x);

    float4 a  = xr[w*32 + lane];
    float  sn = g_self[w];
    float4 acc = make_float4(a.x*sn, a.y*sn, a.z*sn, a.w*sn);

    int s = g_rowstart[w];
    int e = g_rowstart[w+1];
    int j = s;
    for (; j + 4 <= e; j += 4) {
        int   s0 = g_csr_src[j],   s1 = g_csr_src[j+1];
        int   s2 = g_csr_src[j+2], s3 = g_csr_src[j+3];
        float w0 = g_csr_w[j],     w1 = g_csr_w[j+1];
        float w2 = g_csr_w[j+2],   w3 = g_csr_w[j+3];
        float4 u0 = xr[s0*32 + lane];
        float4 u1 = xr[s1*32 + lane];
        float4 u2 = xr[s2*32 + lane];
        float4 u3 = xr[s3*32 + lane];
        acc.x = fmaf(u0.x, w0, acc.x); acc.y = fmaf(u0.y, w0, acc.y);
        acc.z = fmaf(u0.z, w0, acc.z); acc.w = fmaf(u0.w, w0, acc.w);
        acc.x = fmaf(u1.x, w1, acc.x); acc.y = fmaf(u1.y, w1, acc.y);
        acc.z = fmaf(u1.z, w1, acc.z); acc.w = fmaf(u1.w, w1, acc.w);
        acc.x = fmaf(u2.x, w2, acc.x); acc.y = fmaf(u2.y, w2, acc.y);
        acc.z = fmaf(u2.z, w2, acc.z); acc.w = fmaf(u2.w, w2, acc.w);
        acc.x = fmaf(u3.x, w3, acc.x); acc.y = fmaf(u3.y, w3, acc.y);
        acc.z = fmaf(u3.z, w3, acc.z); acc.w = fmaf(u3.w, w3, acc.w);
    }
    for (; j < e; j++) {
        int   src = g_csr_src[j];
        float wt  = g_csr_w[j];
        float4 u  = xr[src*32 + lane];
        acc.x = fmaf(u.x, wt, acc.x);
        acc.y = fmaf(u.y, wt, acc.y);
        acc.z = fmaf(u.z, wt, acc.z);
        acc.w = fmaf(u.w, wt, acc.w);
    }

    // split into bf16 hi/lo, pack interleaved: {hi01, lo01, hi23, lo23}
    float vv[4] = {acc.x, acc.y, acc.z, acc.w};
    __nv_bfloat16 hi[4], lo[4];
    #pragma unroll
    for (int q = 0; q < 4; q++) {
        hi[q] = __float2bfloat16_rn(vv[q]);
        lo[q] = __float2bfloat16_rn(vv[q] - __bfloat162float(hi[q]));
    }
    uint4 p;
    p.x = ((uint32_t)__bfloat16_as_ushort(hi[1]) << 16) | __bfloat16_as_ushort(hi[0]);
    p.y = ((uint32_t)__bfloat16_as_ushort(lo[1]) << 16) | __bfloat16_as_ushort(lo[0]);
    p.z = ((uint32_t)__bfloat16_as_ushort(hi[3]) << 16) | __bfloat16_as_ushort(hi[2]);
    p.w = ((uint32_t)__bfloat16_as_ushort(lo[3]) << 16) | __bfloat16_as_ushort(lo[2]);
    reinterpret_cast<uint4*>(g_apk)[w*32 + lane] = p;
}

// ---------------- bf16 mma.sync GEMM: out = relu((Ahi+Alo)(Whi+Wlo)^T + b) ----------------
__device__ __forceinline__ void mma_bf16(float* d, const uint32_t* a, const uint32_t* b)
{
    asm volatile(
        "mma.sync.aligned.m16n8k16.row.col.f32.bf16.bf16.f32 "
        "{%0,%1,%2,%3}, {%4,%5,%6,%7}, {%8,%9}, {%0,%1,%2,%3};"
        : "+f"(d[0]), "+f"(d[1]), "+f"(d[2]), "+f"(d[3])
        : "r"(a[0]), "r"(a[1]), "r"(a[2]), "r"(a[3]), "r"(b[0]), "r"(b[1]));
}

template<bool LAST>
__global__ __launch_bounds__(256)
void k_gemm_mma(const __nv_bfloat16* __restrict__ apk,
                const __nv_bfloat16* __restrict__ wpk,
                const float* __restrict__ bias,
                float* __restrict__ out,
                const int* __restrict__ batch)
{
    int tid    = threadIdx.x;
    int lane   = tid & 31;
    int wid    = tid >> 5;
    int warp_m = wid & 3;        // 0..3
    int warp_n = wid >> 2;       // 0..1
    int g      = lane >> 2;      // groupID 0..7
    int tq     = lane & 3;       // quad lane 0..3

    int rowBase = blockIdx.x * TILE_M + warp_m * 32;   // < NNP always
    int colBase = warp_n * 64;

    // uint2 view: row has 64 uint2 entries, entry o = {hi_word(o), lo_word(o)}
    const uint2* AP = reinterpret_cast<const uint2*>(apk);
    const uint2* BP = reinterpret_cast<const uint2*>(wpk);

    const uint2* a0 = AP + (rowBase + g     ) * 64;
    const uint2* a1 = AP + (rowBase + g +  8) * 64;
    const uint2* a2 = AP + (rowBase + g + 16) * 64;
    const uint2* a3 = AP + (rowBase + g + 24) * 64;
    const uint2* bp = BP + (colBase + g) * 64;

    float d[2][8][4];
    #pragma unroll
    for (int mt = 0; mt < 2; mt++)
        #pragma unroll
        for (int nt = 0; nt < 8; nt++)
            #pragma unroll
            for (int q = 0; q < 4; q++) d[mt][nt][q] = 0.0f;

    #pragma unroll 4
    for (int ks = 0; ks < 8; ks++) {
        int o0 = ks*8 + tq;
        int o1 = o0 + 4;

        uint2 v00 = a0[o0], v01 = a0[o1];
        uint2 v10 = a1[o0], v11 = a1[o1];
        uint2 v20 = a2[o0], v21 = a2[o1];
        uint2 v30 = a3[o0], v31 = a3[o1];

        uint32_t aH[2][4], aL[2][4];
        aH[0][0] = v00.x; aH[0][1] = v10.x; aH[0][2] = v01.x; aH[0][3] = v11.x;
        aH[1][0] = v20.x; aH[1][1] = v30.x; aH[1][2] = v21.x; aH[1][3] = v31.x;
        aL[0][0] = v00.y; aL[0][1] = v10.y; aL[0][2] = v01.y; aL[0][3] = v11.y;
        aL[1][0] = v20.y; aL[1][1] = v30.y; aL[1][2] = v21.y; aL[1][3] = v31.y;

        uint32_t bHf[8][2], bLf[8][2];
        #pragma unroll
        for (int nt = 0; nt < 8; nt++) {
            uint2 w0 = bp[nt*512 + o0];
            uint2 w1 = bp[nt*512 + o1];
            bHf[nt][0] = w0.x; bHf[nt][1] = w1.x;
            bLf[nt][0] = w0.y; bLf[nt][1] = w1.y;
        }
        #pragma unroll
        for (int mt = 0; mt < 2; mt++)
            #pragma unroll
            for (int nt = 0; nt < 8; nt++)
                mma_bf16(d[mt][nt], aH[mt], bHf[nt]);
        #pragma unroll
        for (int mt = 0; mt < 2; mt++)
            #pragma unroll
            for (int nt = 0; nt < 8; nt++)
                mma_bf16(d[mt][nt], aL[mt], bHf[nt]);
        #pragma unroll
        for (int mt = 0; mt < 2; mt++)
            #pragma unroll
            for (int nt = 0; nt < 8; nt++)
                mma_bf16(d[mt][nt], aH[mt], bLf[nt]);
    }

    // epilogue: bias + relu; LAST scatters into dense output
    #pragma unroll
    for (int mt = 0; mt < 2; mt++) {
        int m0 = rowBase + mt*16 + g;
        int m1 = m0 + 8;
        int or0 = m0, or1 = m1;
        if (LAST) {
            if (m0 < NN) { int b = batch[m0]; or0 = b*MAXA + (m0 - g_ptr[b]); }
            if (m1 < NN) { int b = batch[m1]; or1 = b*MAXA + (m1 - g_ptr[b]); }
        }
        #pragma unroll
        for (int nt = 0; nt < 8; nt++) {
            int cn = colBase + nt*8 + tq*2;
            float2 bv = *reinterpret_cast<const float2*>(bias + cn);
            if (m0 < NN) {
                float2 o;
                o.x = fmaxf(d[mt][nt][0] + bv.x, 0.f);
                o.y = fmaxf(d[mt][nt][1] + bv.y, 0.f);
                *reinterpret_cast<float2*>(out + or0*DD + cn) = o;
            }
            if (m1 < NN) {
                float2 o;
                o.x = fmaxf(d[mt][nt][2] + bv.x, 0.f);
                o.y = fmaxf(d[mt][nt][3] + bv.y, 0.f);
                *reinterpret_cast<float2*>(out + or1*DD + cn) = o;
            }
        }
    }
}

// ---------------- tail zero (only for any region beyond dense+mask) ----------------
__global__ void k_zero_tail(float* __restrict__ out, int start, int n)
{
    int i = blockIdx.x * blockDim.x + threadIdx.x;
    if (i < n) out[start + i] = 0.0f;
}

// ---------------- launch ----------------
extern "C" void kernel_launch(void* const* d_in, const int* in_sizes, int n_in,
                              void* d_out, int out_size)
{
    const float* atoms = (const float*)d_in[0];
    const int*   conn  = (const int*)d_in[1];
    const int*   batch = (const int*)d_in[2];
    const float* W_exp = (const float*)d_in[3];
    const float* b_exp = (const float*)d_in[4];
    const float* Ws    = (const float*)d_in[5];
    const float* bs    = (const float*)d_in[6];
    float* out = (float*)d_out;

    float *px;
    __nv_bfloat16 *papk, *pwpk;
    cudaGetSymbolAddress((void**)&px,   g_x);
    cudaGetSymbolAddress((void**)&papk, g_apk);
    cudaGetSymbolAddress((void**)&pwpk, g_wpk);

    k_zero<<<(NN + 255)/256, 256>>>();
    k_hist<<<(EE + 255)/256, 256>>>(conn + EE, batch);
    k_scan1<<<SCAN_NB, SCAN_BS>>>();
    k_scan2<<<1, 512>>>();
    k_scan3<<<SCAN_NB, SCAN_BS>>>();
    k_csr<<<(EE + 255)/256, 256>>>(conn, batch, out, out_size);
    k_prepw<<<(NLAYERS*DD*DD + 255)/256, 256>>>(Ws);
    k_expand<<<4096, DD>>>(atoms, W_exp, b_exp);

    // any bytes past dense+mask must still be zeroed (normally none)
    int tail = out_size - (DENSE + MASKN);
    if (tail > 0)
        k_zero_tail<<<(tail + 255)/256, 256>>>(out, DENSE + MASKN, tail);

    int aggBlocks = (NN*32 + 255)/256;
    for (int l = 0; l < NLAYERS - 1; l++) {
        k_agg<<<aggBlocks, 256>>>(px);
        k_gemm_mma<false><<<GEMM_NB, 256>>>(papk, pwpk + l*DD*DD*2, bs + l*DD, px, batch);
    }
    k_agg<<<aggBlocks, 256>>>(px);
    k_gemm_mma<true><<<GEMM_NB, 256>>>(papk, pwpk + 4*DD*DD*2, bs + 4*DD, out, batch);
}

// round 8
// speedup vs baseline: 2.0993x; 1.0478x over previous
#include <cuda_runtime.h>
#include <cuda_bf16.h>
#include <cuda_fp16.h>
#include <cstdint>

#define NN   50000
#define EE   600000
#define FEAT 11
#define DD   128
#define BBATCH 500
#define MAXA 100
#define NLAYERS 5
#define DENSE (BBATCH*MAXA*DD)   /* 6,400,000 */
#define MASKN (BBATCH*MAXA)      /* 50,000 */

#define SCAN_BS   1024
#define SCAN_NB   ((NN + SCAN_BS - 1) / SCAN_BS)   /* 49 */

#define TILE_M    128
#define GEMM_NB   ((NN + TILE_M - 1) / TILE_M)     /* 391 */
#define NNP       (GEMM_NB * TILE_M)               /* 50048, padded */

// -------- scratch (static device globals; zero-initialized, no runtime alloc) --------
__device__ __half g_y[NN*DD];                      // y = dinv * x, fp16 (12.8 MB)
__device__ __nv_bfloat16 g_apk[NNP*DD*2];          // packed agg: {hi01, lo01, hi23, lo23}
__device__ __nv_bfloat16 g_wpk[NLAYERS*DD*DD*2];   // packed Wt [l][n], same interleave
__device__ float g_dinv[NN];
__device__ int   g_deg[NN];
__device__ int   g_rowstart[NN+1];
__device__ int   g_cursor[NN];
__device__ int   g_csr_src[EE];
__device__ int   g_counts[BBATCH];
__device__ int   g_ptr[BBATCH];
__device__ int   g_bsum[SCAN_NB];
__device__ int   g_boff[SCAN_NB];

// ---------------- graph preprocessing ----------------
__global__ void k_zero()
{
    int i = blockIdx.x * blockDim.x + threadIdx.x;
    if (i < NN) g_deg[i] = 0;
    if (i < BBATCH) g_counts[i] = 0;
}

__global__ void k_hist(const int* __restrict__ col, const int* __restrict__ batch)
{
    int i = blockIdx.x * blockDim.x + threadIdx.x;
    if (i < EE) atomicAdd(&g_deg[col[i]], 1);
    if (i < NN) atomicAdd(&g_counts[batch[i]], 1);
}

// scan1 also computes dinv (deg value already in hand)
__global__ __launch_bounds__(SCAN_BS)
void k_scan1()
{
    __shared__ int warp_sums[32];
    int tid  = threadIdx.x;
    int lane = tid & 31;
    int wid  = tid >> 5;
    int i    = blockIdx.x * SCAN_BS + tid;

    int v0 = (i < NN) ? g_deg[i] : 0;
    if (i < NN) {
        g_dinv[i] = rsqrtf((float)v0 + 2.0f);
    }
    int v  = v0;
    #pragma unroll
    for (int off = 1; off < 32; off <<= 1) {
        int t = __shfl_up_sync(0xffffffffu, v, off);
        if (lane >= off) v += t;
    }
    if (lane == 31) warp_sums[wid] = v;
    __syncthreads();
    if (wid == 0) {
        int s = warp_sums[lane];
        #pragma unroll
        for (int off = 1; off < 32; off <<= 1) {
            int t = __shfl_up_sync(0xffffffffu, s, off);
            if (lane >= off) s += t;
        }
        warp_sums[lane] = s;
    }
    __syncthreads();
    int incl = v + (wid ? warp_sums[wid-1] : 0);
    if (i < NN) {
        g_rowstart[i+1] = incl;
        g_cursor[i]     = incl - v0;
    }
    if (tid == SCAN_BS - 1) g_bsum[blockIdx.x] = incl;
}

__global__ __launch_bounds__(512)
void k_scan2()
{
    __shared__ int sb[64];
    __shared__ int warp_sums[16];
    int tid  = threadIdx.x;
    int lane = tid & 31;
    int wid  = tid >> 5;

    if (tid < 64) sb[tid] = (tid < SCAN_NB) ? g_bsum[tid] : 0;
    __syncthreads();
    #pragma unroll
    for (int off = 1; off < 64; off <<= 1) {
        int t = 0;
        if (tid < 64 && tid >= off) t = sb[tid - off];
        __syncthreads();
        if (tid < 64) sb[tid] += t;
        __syncthreads();
    }
    if (tid < SCAN_NB) g_boff[tid] = (tid == 0) ? 0 : sb[tid - 1];
    if (tid == 0) g_rowstart[0] = 0;

    int c = (tid < BBATCH) ? g_counts[tid] : 0;
    int v = c;
    #pragma unroll
    for (int off = 1; off < 32; off <<= 1) {
        int t = __shfl_up_sync(0xffffffffu, v, off);
        if (lane >= off) v += t;
    }
    if (lane == 31) warp_sums[wid] = v;
    __syncthreads();
    if (wid == 0 && lane < 16) {
        int s = warp_sums[lane];
        #pragma unroll
        for (int off = 1; off < 16; off <<= 1) {
            int t = __shfl_up_sync(0xffffu, s, off);
            if (lane >= off) s += t;
        }
        warp_sums[lane] = s;
    }
    __syncthreads();
    int incl = v + (wid ? warp_sums[wid-1] : 0);
    if (tid < BBATCH) g_ptr[tid] = incl - c;
}

__global__ __launch_bounds__(SCAN_BS)
void k_scan3()
{
    int i = blockIdx.x * SCAN_BS + threadIdx.x;
    if (i >= NN) return;
    int off = g_boff[blockIdx.x];
    g_rowstart[i+1] += off;
    g_cursor[i]     += off;
}

// csr build (indices only now) + mask write
__global__ void k_csr(const int* __restrict__ conn, const int* __restrict__ batch,
                      float* __restrict__ out, int out_size)
{
    int e = blockIdx.x * blockDim.x + threadIdx.x;
    if (e < NN && out_size >= DENSE + MASKN) {
        int b = batch[e];
        out[DENSE + b*MAXA + (e - g_ptr[b])] = 1.0f;
    }
    if (e >= EE) return;
    int r = conn[e];
    int c = conn[EE + e];
    int slot = atomicAdd(&g_cursor[c], 1);
    g_csr_src[slot] = r;
}

// ---- transpose W to [l][n][k], split bf16 hi/lo, interleave per word-pair ----
__global__ void k_prepw(const float* __restrict__ Ws)
{
    int idx = blockIdx.x * blockDim.x + threadIdx.x;
    if (idx >= NLAYERS*DD*DD) return;
    int l = idx >> 14;
    int r = idx & 16383;
    int n = r >> 7;
    int k = r & 127;
    float v = Ws[l*DD*DD + k*DD + n];
    __nv_bfloat16 hi = __float2bfloat16_rn(v);
    __nv_bfloat16 lo = __float2bfloat16_rn(v - __bfloat162float(hi));
    int base = (l*DD + n) * 256 + (k >> 1) * 4 + (k & 1);
    g_wpk[base]     = hi;
    g_wpk[base + 2] = lo;
}

// ---------------- log-expansion: y0 = dinv * (log(atoms+1) @ W_exp + b_exp) ----------------
__global__ void k_expand(const float* __restrict__ atoms,
                         const float* __restrict__ Wexp,
                         const float* __restrict__ bexp)
{
    __shared__ float sW[FEAT*DD];
    __shared__ float sb[DD];
    __shared__ float la[FEAT];
    int tid = threadIdx.x;
    for (int i = tid; i < FEAT*DD; i += DD) sW[i] = Wexp[i];
    sb[tid] = bexp[tid];
    for (int n = blockIdx.x; n < NN; n += gridDim.x) {
        __syncthreads();
        if (tid < FEAT) la[tid] = logf(atoms[n*FEAT + tid] + 1.0f);
        __syncthreads();
        float acc = sb[tid];
        #pragma unroll
        for (int f = 0; f < FEAT; f++) acc = fmaf(la[f], sW[f*DD + tid], acc);
        g_y[n*DD + tid] = __float2half(acc * g_dinv[n]);
    }
}

// ------- aggregation: agg[w] = dinv[w]*(sum_src y[src] + 2*y[w]), packed bf16 hi/lo -------
__global__ void k_agg(const __half* __restrict__ y)
{
    int w = (blockIdx.x * blockDim.x + threadIdx.x) >> 5;
    if (w >= NN) return;
    int lane = threadIdx.x & 31;
    const uint2* yr = reinterpret_cast<const uint2*>(y);   // 32 uint2 per row (4 halves each)

    uint2 sv = yr[w*32 + lane];
    float2 s0 = __half22float2(*reinterpret_cast<__half2*>(&sv.x));
    float2 s1 = __half22float2(*reinterpret_cast<__half2*>(&sv.y));
    float4 acc = make_float4(2.f*s0.x, 2.f*s0.y, 2.f*s1.x, 2.f*s1.y);

    int s = g_rowstart[w];
    int e = g_rowstart[w+1];
    int j = s;
    for (; j + 4 <= e; j += 4) {
        int   i0 = g_csr_src[j],   i1 = g_csr_src[j+1];
        int   i2 = g_csr_src[j+2], i3 = g_csr_src[j+3];
        uint2 u0 = yr[i0*32 + lane];
        uint2 u1 = yr[i1*32 + lane];
        uint2 u2 = yr[i2*32 + lane];
        uint2 u3 = yr[i3*32 + lane];
        float2 a0 = __half22float2(*reinterpret_cast<__half2*>(&u0.x));
        float2 b0 = __half22float2(*reinterpret_cast<__half2*>(&u0.y));
        float2 a1 = __half22float2(*reinterpret_cast<__half2*>(&u1.x));
        float2 b1 = __half22float2(*reinterpret_cast<__half2*>(&u1.y));
        float2 a2 = __half22float2(*reinterpret_cast<__half2*>(&u2.x));
        float2 b2 = __half22float2(*reinterpret_cast<__half2*>(&u2.y));
        float2 a3 = __half22float2(*reinterpret_cast<__half2*>(&u3.x));
        float2 b3 = __half22float2(*reinterpret_cast<__half2*>(&u3.y));
        acc.x += a0.x + a1.x + a2.x + a3.x;
        acc.y += a0.y + a1.y + a2.y + a3.y;
        acc.z += b0.x + b1.x + b2.x + b3.x;
        acc.w += b0.y + b1.y + b2.y + b3.y;
    }
    for (; j < e; j++) {
        int   src = g_csr_src[j];
        uint2 u   = yr[src*32 + lane];
        float2 a  = __half22float2(*reinterpret_cast<__half2*>(&u.x));
        float2 b  = __half22float2(*reinterpret_cast<__half2*>(&u.y));
        acc.x += a.x; acc.y += a.y; acc.z += b.x; acc.w += b.y;
    }

    float di = g_dinv[w];
    float vv[4] = {acc.x*di, acc.y*di, acc.z*di, acc.w*di};
    __nv_bfloat16 hi[4], lo[4];
    #pragma unroll
    for (int q = 0; q < 4; q++) {
        hi[q] = __float2bfloat16_rn(vv[q]);
        lo[q] = __float2bfloat16_rn(vv[q] - __bfloat162float(hi[q]));
    }
    uint4 p;
    p.x = ((uint32_t)__bfloat16_as_ushort(hi[1]) << 16) | __bfloat16_as_ushort(hi[0]);
    p.y = ((uint32_t)__bfloat16_as_ushort(lo[1]) << 16) | __bfloat16_as_ushort(lo[0]);
    p.z = ((uint32_t)__bfloat16_as_ushort(hi[3]) << 16) | __bfloat16_as_ushort(hi[2]);
    p.w = ((uint32_t)__bfloat16_as_ushort(lo[3]) << 16) | __bfloat16_as_ushort(lo[2]);
    reinterpret_cast<uint4*>(g_apk)[w*32 + lane] = p;
}

// ---------------- bf16 mma.sync GEMM: relu((Ahi+Alo)(Whi+Wlo)^T + b) ----------------
__device__ __forceinline__ void mma_bf16(float* d, const uint32_t* a, const uint32_t* b)
{
    asm volatile(
        "mma.sync.aligned.m16n8k16.row.col.f32.bf16.bf16.f32 "
        "{%0,%1,%2,%3}, {%4,%5,%6,%7}, {%8,%9}, {%0,%1,%2,%3};"
        : "+f"(d[0]), "+f"(d[1]), "+f"(d[2]), "+f"(d[3])
        : "r"(a[0]), "r"(a[1]), "r"(a[2]), "r"(a[3]), "r"(b[0]), "r"(b[1]));
}

// non-LAST: writes y = dinv*relu(..) as fp16. LAST: scatters fp32 into dense out.
template<bool LAST>
__global__ __launch_bounds__(256)
void k_gemm_mma(const __nv_bfloat16* __restrict__ apk,
                const __nv_bfloat16* __restrict__ wpk,
                const float* __restrict__ bias,
                __half* __restrict__ yout,
                float* __restrict__ dout,
                const int* __restrict__ batch)
{
    int tid    = threadIdx.x;
    int lane   = tid & 31;
    int wid    = tid >> 5;
    int warp_m = wid & 3;
    int warp_n = wid >> 2;
    int g      = lane >> 2;
    int tq     = lane & 3;

    int rowBase = blockIdx.x * TILE_M + warp_m * 32;
    int colBase = warp_n * 64;

    const uint2* AP = reinterpret_cast<const uint2*>(apk);
    const uint2* BP = reinterpret_cast<const uint2*>(wpk);

    const uint2* a0 = AP + (rowBase + g     ) * 64;
    const uint2* a1 = AP + (rowBase + g +  8) * 64;
    const uint2* a2 = AP + (rowBase + g + 16) * 64;
    const uint2* a3 = AP + (rowBase + g + 24) * 64;
    const uint2* bp = BP + (colBase + g) * 64;

    float d[2][8][4];
    #pragma unroll
    for (int mt = 0; mt < 2; mt++)
        #pragma unroll
        for (int nt = 0; nt < 8; nt++)
            #pragma unroll
            for (int q = 0; q < 4; q++) d[mt][nt][q] = 0.0f;

    #pragma unroll 4
    for (int ks = 0; ks < 8; ks++) {
        int o0 = ks*8 + tq;
        int o1 = o0 + 4;

        uint2 v00 = a0[o0], v01 = a0[o1];
        uint2 v10 = a1[o0], v11 = a1[o1];
        uint2 v20 = a2[o0], v21 = a2[o1];
        uint2 v30 = a3[o0], v31 = a3[o1];

        uint32_t aH[2][4], aL[2][4];
        aH[0][0] = v00.x; aH[0][1] = v10.x; aH[0][2] = v01.x; aH[0][3] = v11.x;
        aH[1][0] = v20.x; aH[1][1] = v30.x; aH[1][2] = v21.x; aH[1][3] = v31.x;
        aL[0][0] = v00.y; aL[0][1] = v10.y; aL[0][2] = v01.y; aL[0][3] = v11.y;
        aL[1][0] = v20.y; aL[1][1] = v30.y; aL[1][2] = v21.y; aL[1][3] = v31.y;

        uint32_t bHf[8][2], bLf[8][2];
        #pragma unroll
        for (int nt = 0; nt < 8; nt++) {
            uint2 w0 = bp[nt*512 + o0];
            uint2 w1 = bp[nt*512 + o1];
            bHf[nt][0] = w0.x; bHf[nt][1] = w1.x;
            bLf[nt][0] = w0.y; bLf[nt][1] = w1.y;
        }
        #pragma unroll
        for (int mt = 0; mt < 2; mt++)
            #pragma unroll
            for (int nt = 0; nt < 8; nt++)
                mma_bf16(d[mt][nt], aH[mt], bHf[nt]);
        #pragma unroll
        for (int mt = 0; mt < 2; mt++)
            #pragma unroll
            for (int nt = 0; nt < 8; nt++)
                mma_bf16(d[mt][nt], aL[mt], bHf[nt]);
        #pragma unroll
        for (int mt = 0; mt < 2; mt++)
            #pragma unroll
            for (int nt = 0; nt < 8; nt++)
                mma_bf16(d[mt][nt], aH[mt], bLf[nt]);
    }

    #pragma unroll
    for (int mt = 0; mt < 2; mt++) {
        int m0 = rowBase + mt*16 + g;
        int m1 = m0 + 8;
        if (LAST) {
            int or0 = 0, or1 = 0;
            if (m0 < NN) { int b = batch[m0]; or0 = b*MAXA + (m0 - g_ptr[b]); }
            if (m1 < NN) { int b = batch[m1]; or1 = b*MAXA + (m1 - g_ptr[b]); }
            #pragma unroll
            for (int nt = 0; nt < 8; nt++) {
                int cn = colBase + nt*8 + tq*2;
                float2 bv = *reinterpret_cast<const float2*>(bias + cn);
                if (m0 < NN) {
                    float2 o;
                    o.x = fmaxf(d[mt][nt][0] + bv.x, 0.f);
                    o.y = fmaxf(d[mt][nt][1] + bv.y, 0.f);
                    *reinterpret_cast<float2*>(dout + or0*DD + cn) = o;
                }
                if (m1 < NN) {
                    float2 o;
                    o.x = fmaxf(d[mt][nt][2] + bv.x, 0.f);
                    o.y = fmaxf(d[mt][nt][3] + bv.y, 0.f);
                    *reinterpret_cast<float2*>(dout + or1*DD + cn) = o;
                }
            }
        } else {
            float di0 = (m0 < NN) ? g_dinv[m0] : 0.f;
            float di1 = (m1 < NN) ? g_dinv[m1] : 0.f;
            #pragma unroll
            for (int nt = 0; nt < 8; nt++) {
                int cn = colBase + nt*8 + tq*2;
                float2 bv = *reinterpret_cast<const float2*>(bias + cn);
                if (m0 < NN) {
                    float ox = fmaxf(d[mt][nt][0] + bv.x, 0.f) * di0;
                    float oy = fmaxf(d[mt][nt][1] + bv.y, 0.f) * di0;
                    *reinterpret_cast<__half2*>(yout + m0*DD + cn) = __floats2half2_rn(ox, oy);
                }
                if (m1 < NN) {
                    float ox = fmaxf(d[mt][nt][2] + bv.x, 0.f) * di1;
                    float oy = fmaxf(d[mt][nt][3] + bv.y, 0.f) * di1;
                    *reinterpret_cast<__half2*>(yout + m1*DD + cn) = __floats2half2_rn(ox, oy);
                }
            }
        }
    }
}

// ---------------- tail zero (only for any region beyond dense+mask) ----------------
__global__ void k_zero_tail(float* __restrict__ out, int start, int n)
{
    int i = blockIdx.x * blockDim.x + threadIdx.x;
    if (i < n) out[start + i] = 0.0f;
}

// ---------------- launch ----------------
extern "C" void kernel_launch(void* const* d_in, const int* in_sizes, int n_in,
                              void* d_out, int out_size)
{
    const float* atoms = (const float*)d_in[0];
    const int*   conn  = (const int*)d_in[1];
    const int*   batch = (const int*)d_in[2];
    const float* W_exp = (const float*)d_in[3];
    const float* b_exp = (const float*)d_in[4];
    const float* Ws    = (const float*)d_in[5];
    const float* bs    = (const float*)d_in[6];
    float* out = (float*)d_out;

    __half *py;
    __nv_bfloat16 *papk, *pwpk;
    cudaGetSymbolAddress((void**)&py,   g_y);
    cudaGetSymbolAddress((void**)&papk, g_apk);
    cudaGetSymbolAddress((void**)&pwpk, g_wpk);

    k_zero<<<(NN + 255)/256, 256>>>();
    k_hist<<<(EE + 255)/256, 256>>>(conn + EE, batch);
    k_scan1<<<SCAN_NB, SCAN_BS>>>();
    k_scan2<<<1, 512>>>();
    k_scan3<<<SCAN_NB, SCAN_BS>>>();
    k_csr<<<(EE + 255)/256, 256>>>(conn, batch, out, out_size);
    k_prepw<<<(NLAYERS*DD*DD + 255)/256, 256>>>(Ws);
    k_expand<<<4096, DD>>>(atoms, W_exp, b_exp);

    int tail = out_size - (DENSE + MASKN);
    if (tail > 0)
        k_zero_tail<<<(tail + 255)/256, 256>>>(out, DENSE + MASKN, tail);

    int aggBlocks = (NN*32 + 255)/256;
    for (int l = 0; l < NLAYERS - 1; l++) {
        k_agg<<<aggBlocks, 256>>>(py);
        k_gemm_mma<false><<<GEMM_NB, 256>>>(papk, pwpk + l*DD*DD*2, bs + l*DD, py, nullptr, batch);
    }
    k_agg<<<aggBlocks, 256>>>(py);
    k_gemm_mma<true><<<GEMM_NB, 256>>>(papk, pwpk + 4*DD*DD*2, bs + 4*DD, nullptr, out, batch);
}

// round 9
// speedup vs baseline: 2.3440x; 1.1166x over previous
#include <cuda_runtime.h>
#include <cuda_fp16.h>
#include <cstdint>

#define NN   50000
#define EE   600000
#define FEAT 11
#define DD   128
#define BBATCH 500
#define MAXA 100
#define NLAYERS 5
#define DENSE (BBATCH*MAXA*DD)   /* 6,400,000 */
#define MASKN (BBATCH*MAXA)      /* 50,000 */

#define SCAN_BS   1024
#define SCAN_NB   ((NN + SCAN_BS - 1) / SCAN_BS)   /* 49 */

#define TILE_M    128
#define GEMM_NB   ((NN + TILE_M - 1) / TILE_M)     /* 391 */
#define NNP       (GEMM_NB * TILE_M)               /* 50048, padded */

// -------- scratch (static device globals; zero-initialized, no runtime alloc) --------
__device__ __half g_y[NN*DD];                  // y = dinv * x, fp16 (12.8 MB)
__device__ __half g_apk[NNP*DD];               // aggregated A, fp16 (12.8 MB; pad rows stay 0)
__device__ __half g_wpk[NLAYERS*DD*DD*2];      // packed Wt [l][n]: {hi01, lo01, hi23, lo23}
__device__ float g_dinv[NN];
__device__ int   g_deg[NN];
__device__ int   g_rowstart[NN+1];
__device__ int   g_cursor[NN];
__device__ int   g_csr_src[EE];
__device__ int   g_counts[BBATCH];
__device__ int   g_ptr[BBATCH];
__device__ int   g_bsum[SCAN_NB];
__device__ int   g_boff[SCAN_NB];

// ---------------- graph preprocessing ----------------
__global__ void k_zero()
{
    int i = blockIdx.x * blockDim.x + threadIdx.x;
    if (i < NN) g_deg[i] = 0;
    if (i < BBATCH) g_counts[i] = 0;
}

__global__ void k_hist(const int* __restrict__ col, const int* __restrict__ batch)
{
    int i = blockIdx.x * blockDim.x + threadIdx.x;
    if (i < EE) atomicAdd(&g_deg[col[i]], 1);
    if (i < NN) atomicAdd(&g_counts[batch[i]], 1);
}

// scan1 also computes dinv (deg value already in hand)
__global__ __launch_bounds__(SCAN_BS)
void k_scan1()
{
    __shared__ int warp_sums[32];
    int tid  = threadIdx.x;
    int lane = tid & 31;
    int wid  = tid >> 5;
    int i    = blockIdx.x * SCAN_BS + tid;

    int v0 = (i < NN) ? g_deg[i] : 0;
    if (i < NN) {
        g_dinv[i] = rsqrtf((float)v0 + 2.0f);
    }
    int v  = v0;
    #pragma unroll
    for (int off = 1; off < 32; off <<= 1) {
        int t = __shfl_up_sync(0xffffffffu, v, off);
        if (lane >= off) v += t;
    }
    if (lane == 31) warp_sums[wid] = v;
    __syncthreads();
    if (wid == 0) {
        int s = warp_sums[lane];
        #pragma unroll
        for (int off = 1; off < 32; off <<= 1) {
            int t = __shfl_up_sync(0xffffffffu, s, off);
            if (lane >= off) s += t;
        }
        warp_sums[lane] = s;
    }
    __syncthreads();
    int incl = v + (wid ? warp_sums[wid-1] : 0);
    if (i < NN) {
        g_rowstart[i+1] = incl;
        g_cursor[i]     = incl - v0;
    }
    if (tid == SCAN_BS - 1) g_bsum[blockIdx.x] = incl;
}

__global__ __launch_bounds__(512)
void k_scan2()
{
    __shared__ int sb[64];
    __shared__ int warp_sums[16];
    int tid  = threadIdx.x;
    int lane = tid & 31;
    int wid  = tid >> 5;

    if (tid < 64) sb[tid] = (tid < SCAN_NB) ? g_bsum[tid] : 0;
    __syncthreads();
    #pragma unroll
    for (int off = 1; off < 64; off <<= 1) {
        int t = 0;
        if (tid < 64 && tid >= off) t = sb[tid - off];
        __syncthreads();
        if (tid < 64) sb[tid] += t;
        __syncthreads();
    }
    if (tid < SCAN_NB) g_boff[tid] = (tid == 0) ? 0 : sb[tid - 1];
    if (tid == 0) g_rowstart[0] = 0;

    int c = (tid < BBATCH) ? g_counts[tid] : 0;
    int v = c;
    #pragma unroll
    for (int off = 1; off < 32; off <<= 1) {
        int t = __shfl_up_sync(0xffffffffu, v, off);
        if (lane >= off) v += t;
    }
    if (lane == 31) warp_sums[wid] = v;
    __syncthreads();
    if (wid == 0 && lane < 16) {
        int s = warp_sums[lane];
        #pragma unroll
        for (int off = 1; off < 16; off <<= 1) {
            int t = __shfl_up_sync(0xffffu, s, off);
            if (lane >= off) s += t;
        }
        warp_sums[lane] = s;
    }
    __syncthreads();
    int incl = v + (wid ? warp_sums[wid-1] : 0);
    if (tid < BBATCH) g_ptr[tid] = incl - c;
}

__global__ __launch_bounds__(SCAN_BS)
void k_scan3()
{
    int i = blockIdx.x * SCAN_BS + threadIdx.x;
    if (i >= NN) return;
    int off = g_boff[blockIdx.x];
    g_rowstart[i+1] += off;
    g_cursor[i]     += off;
}

// csr build (indices only) + mask write
__global__ void k_csr(const int* __restrict__ conn, const int* __restrict__ batch,
                      float* __restrict__ out, int out_size)
{
    int e = blockIdx.x * blockDim.x + threadIdx.x;
    if (e < NN && out_size >= DENSE + MASKN) {
        int b = batch[e];
        out[DENSE + b*MAXA + (e - g_ptr[b])] = 1.0f;
    }
    if (e >= EE) return;
    int r = conn[e];
    int c = conn[EE + e];
    int slot = atomicAdd(&g_cursor[c], 1);
    g_csr_src[slot] = r;
}

// ---- transpose W to [l][n][k], split fp16 hi/lo, interleave per word-pair ----
__global__ void k_prepw(const float* __restrict__ Ws)
{
    int idx = blockIdx.x * blockDim.x + threadIdx.x;
    if (idx >= NLAYERS*DD*DD) return;
    int l = idx >> 14;
    int r = idx & 16383;
    int n = r >> 7;
    int k = r & 127;
    float v = Ws[l*DD*DD + k*DD + n];
    __half hi = __float2half_rn(v);
    __half lo = __float2half_rn(v - __half2float(hi));
    int base = (l*DD + n) * 256 + (k >> 1) * 4 + (k & 1);
    g_wpk[base]     = hi;
    g_wpk[base + 2] = lo;
}

// ---------------- log-expansion: y0 = dinv * (log(atoms+1) @ W_exp + b_exp) ----------------
__global__ void k_expand(const float* __restrict__ atoms,
                         const float* __restrict__ Wexp,
                         const float* __restrict__ bexp)
{
    __shared__ float sW[FEAT*DD];
    __shared__ float sb[DD];
    __shared__ float la[FEAT];
    int tid = threadIdx.x;
    for (int i = tid; i < FEAT*DD; i += DD) sW[i] = Wexp[i];
    sb[tid] = bexp[tid];
    for (int n = blockIdx.x; n < NN; n += gridDim.x) {
        __syncthreads();
        if (tid < FEAT) la[tid] = logf(atoms[n*FEAT + tid] + 1.0f);
        __syncthreads();
        float acc = sb[tid];
        #pragma unroll
        for (int f = 0; f < FEAT; f++) acc = fmaf(la[f], sW[f*DD + tid], acc);
        g_y[n*DD + tid] = __float2half(acc * g_dinv[n]);
    }
}

// ------- aggregation: agg[w] = dinv[w]*(sum_src y[src] + 2*y[w]), emitted fp16 -------
__global__ void k_agg(const __half* __restrict__ y)
{
    int w = (blockIdx.x * blockDim.x + threadIdx.x) >> 5;
    if (w >= NN) return;
    int lane = threadIdx.x & 31;
    const uint2* yr = reinterpret_cast<const uint2*>(y);   // 32 uint2 per row (4 halves each)

    uint2 sv = yr[w*32 + lane];
    float2 s0 = __half22float2(*reinterpret_cast<__half2*>(&sv.x));
    float2 s1 = __half22float2(*reinterpret_cast<__half2*>(&sv.y));
    float4 acc = make_float4(2.f*s0.x, 2.f*s0.y, 2.f*s1.x, 2.f*s1.y);

    int s = g_rowstart[w];
    int e = g_rowstart[w+1];
    int j = s;
    for (; j + 4 <= e; j += 4) {
        int   i0 = g_csr_src[j],   i1 = g_csr_src[j+1];
        int   i2 = g_csr_src[j+2], i3 = g_csr_src[j+3];
        uint2 u0 = yr[i0*32 + lane];
        uint2 u1 = yr[i1*32 + lane];
        uint2 u2 = yr[i2*32 + lane];
        uint2 u3 = yr[i3*32 + lane];
        float2 a0 = __half22float2(*reinterpret_cast<__half2*>(&u0.x));
        float2 b0 = __half22float2(*reinterpret_cast<__half2*>(&u0.y));
        float2 a1 = __half22float2(*reinterpret_cast<__half2*>(&u1.x));
        float2 b1 = __half22float2(*reinterpret_cast<__half2*>(&u1.y));
        float2 a2 = __half22float2(*reinterpret_cast<__half2*>(&u2.x));
        float2 b2 = __half22float2(*reinterpret_cast<__half2*>(&u2.y));
        float2 a3 = __half22float2(*reinterpret_cast<__half2*>(&u3.x));
        float2 b3 = __half22float2(*reinterpret_cast<__half2*>(&u3.y));
        acc.x += a0.x + a1.x + a2.x + a3.x;
        acc.y += a0.y + a1.y + a2.y + a3.y;
        acc.z += b0.x + b1.x + b2.x + b3.x;
        acc.w += b0.y + b1.y + b2.y + b3.y;
    }
    for (; j < e; j++) {
        int   src = g_csr_src[j];
        uint2 u   = yr[src*32 + lane];
        float2 a  = __half22float2(*reinterpret_cast<__half2*>(&u.x));
        float2 b  = __half22float2(*reinterpret_cast<__half2*>(&u.y));
        acc.x += a.x; acc.y += a.y; acc.z += b.x; acc.w += b.y;
    }

    float di = g_dinv[w];
    __half2 h0 = __floats2half2_rn(acc.x*di, acc.y*di);
    __half2 h1 = __floats2half2_rn(acc.z*di, acc.w*di);
    uint2 p;
    p.x = *reinterpret_cast<uint32_t*>(&h0);
    p.y = *reinterpret_cast<uint32_t*>(&h1);
    reinterpret_cast<uint2*>(g_apk)[w*32 + lane] = p;
}

// ---------------- fp16 mma.sync GEMM: relu(A(Whi+Wlo)^T + b) ----------------
__device__ __forceinline__ void mma_f16(float* d, const uint32_t* a, const uint32_t* b)
{
    asm volatile(
        "mma.sync.aligned.m16n8k16.row.col.f32.f16.f16.f32 "
        "{%0,%1,%2,%3}, {%4,%5,%6,%7}, {%8,%9}, {%0,%1,%2,%3};"
        : "+f"(d[0]), "+f"(d[1]), "+f"(d[2]), "+f"(d[3])
        : "r"(a[0]), "r"(a[1]), "r"(a[2]), "r"(a[3]), "r"(b[0]), "r"(b[1]));
}

// non-LAST: writes y = dinv*relu(..) as fp16. LAST: scatters fp32 into dense out.
template<bool LAST>
__global__ __launch_bounds__(256)
void k_gemm_mma(const __half* __restrict__ apk,
                const __half* __restrict__ wpk,
                const float* __restrict__ bias,
                __half* __restrict__ yout,
                float* __restrict__ dout,
                const int* __restrict__ batch)
{
    int tid    = threadIdx.x;
    int lane   = tid & 31;
    int wid    = tid >> 5;
    int warp_m = wid & 3;
    int warp_n = wid >> 2;
    int g      = lane >> 2;
    int tq     = lane & 3;

    int rowBase = blockIdx.x * TILE_M + warp_m * 32;
    int colBase = warp_n * 64;

    const uint32_t* AP = reinterpret_cast<const uint32_t*>(apk);   // 64 words per row
    const uint2*    BP = reinterpret_cast<const uint2*>(wpk);      // 64 {hi,lo} pairs per row

    const uint32_t* a0 = AP + (rowBase + g     ) * 64;
    const uint32_t* a1 = AP + (rowBase + g +  8) * 64;
    const uint32_t* a2 = AP + (rowBase + g + 16) * 64;
    const uint32_t* a3 = AP + (rowBase + g + 24) * 64;
    const uint2*    bp = BP + (colBase + g) * 64;

    float d[2][8][4];
    #pragma unroll
    for (int mt = 0; mt < 2; mt++)
        #pragma unroll
        for (int nt = 0; nt < 8; nt++)
            #pragma unroll
            for (int q = 0; q < 4; q++) d[mt][nt][q] = 0.0f;

    #pragma unroll 4
    for (int ks = 0; ks < 8; ks++) {
        int o0 = ks*8 + tq;
        int o1 = o0 + 4;

        uint32_t aF[2][4];
        aF[0][0] = a0[o0]; aF[0][1] = a1[o0]; aF[0][2] = a0[o1]; aF[0][3] = a1[o1];
        aF[1][0] = a2[o0]; aF[1][1] = a3[o0]; aF[1][2] = a2[o1]; aF[1][3] = a3[o1];

        uint32_t bHf[8][2], bLf[8][2];
        #pragma unroll
        for (int nt = 0; nt < 8; nt++) {
            uint2 w0 = bp[nt*512 + o0];
            uint2 w1 = bp[nt*512 + o1];
            bHf[nt][0] = w0.x; bHf[nt][1] = w1.x;
            bLf[nt][0] = w0.y; bLf[nt][1] = w1.y;
        }
        #pragma unroll
        for (int mt = 0; mt < 2; mt++)
            #pragma unroll
            for (int nt = 0; nt < 8; nt++)
                mma_f16(d[mt][nt], aF[mt], bHf[nt]);
        #pragma unroll
        for (int mt = 0; mt < 2; mt++)
            #pragma unroll
            for (int nt = 0; nt < 8; nt++)
                mma_f16(d[mt][nt], aF[mt], bLf[nt]);
    }

    #pragma unroll
    for (int mt = 0; mt < 2; mt++) {
        int m0 = rowBase + mt*16 + g;
        int m1 = m0 + 8;
        if (LAST) {
            int or0 = 0, or1 = 0;
            if (m0 < NN) { int b = batch[m0]; or0 = b*MAXA + (m0 - g_ptr[b]); }
            if (m1 < NN) { int b = batch[m1]; or1 = b*MAXA + (m1 - g_ptr[b]); }
            #pragma unroll
            for (int nt = 0; nt < 8; nt++) {
                int cn = colBase + nt*8 + tq*2;
                float2 bv = *reinterpret_cast<const float2*>(bias + cn);
                if (m0 < NN) {
                    float2 o;
                    o.x = fmaxf(d[mt][nt][0] + bv.x, 0.f);
                    o.y = fmaxf(d[mt][nt][1] + bv.y, 0.f);
                    *reinterpret_cast<float2*>(dout + or0*DD + cn) = o;
                }
                if (m1 < NN) {
                    float2 o;
                    o.x = fmaxf(d[mt][nt][2] + bv.x, 0.f);
                    o.y = fmaxf(d[mt][nt][3] + bv.y, 0.f);
                    *reinterpret_cast<float2*>(dout + or1*DD + cn) = o;
                }
            }
        } else {
            float di0 = (m0 < NN) ? g_dinv[m0] : 0.f;
            float di1 = (m1 < NN) ? g_dinv[m1] : 0.f;
            #pragma unroll
            for (int nt = 0; nt < 8; nt++) {
                int cn = colBase + nt*8 + tq*2;
                float2 bv = *reinterpret_cast<const float2*>(bias + cn);
                if (m0 < NN) {
                    float ox = fmaxf(d[mt][nt][0] + bv.x, 0.f) * di0;
                    float oy = fmaxf(d[mt][nt][1] + bv.y, 0.f) * di0;
                    *reinterpret_cast<__half2*>(yout + m0*DD + cn) = __floats2half2_rn(ox, oy);
                }
                if (m1 < NN) {
                    float ox = fmaxf(d[mt][nt][2] + bv.x, 0.f) * di1;
                    float oy = fmaxf(d[mt][nt][3] + bv.y, 0.f) * di1;
                    *reinterpret_cast<__half2*>(yout + m1*DD + cn) = __floats2half2_rn(ox, oy);
                }
            }
        }
    }
}

// ---------------- tail zero (only for any region beyond dense+mask) ----------------
__global__ void k_zero_tail(float* __restrict__ out, int start, int n)
{
    int i = blockIdx.x * blockDim.x + threadIdx.x;
    if (i < n) out[start + i] = 0.0f;
}

// ---------------- launch ----------------
extern "C" void kernel_launch(void* const* d_in, const int* in_sizes, int n_in,
                              void* d_out, int out_size)
{
    const float* atoms = (const float*)d_in[0];
    const int*   conn  = (const int*)d_in[1];
    const int*   batch = (const int*)d_in[2];
    const float* W_exp = (const float*)d_in[3];
    const float* b_exp = (const float*)d_in[4];
    const float* Ws    = (const float*)d_in[5];
    const float* bs    = (const float*)d_in[6];
    float* out = (float*)d_out;

    __half *py, *papk, *pwpk;
    cudaGetSymbolAddress((void**)&py,   g_y);
    cudaGetSymbolAddress((void**)&papk, g_apk);
    cudaGetSymbolAddress((void**)&pwpk, g_wpk);

    k_zero<<<(NN + 255)/256, 256>>>();
    k_hist<<<(EE + 255)/256, 256>>>(conn + EE, batch);
    k_scan1<<<SCAN_NB, SCAN_BS>>>();
    k_scan2<<<1, 512>>>();
    k_scan3<<<SCAN_NB, SCAN_BS>>>();
    k_csr<<<(EE + 255)/256, 256>>>(conn, batch, out, out_size);
    k_prepw<<<(NLAYERS*DD*DD + 255)/256, 256>>>(Ws);
    k_expand<<<4096, DD>>>(atoms, W_exp, b_exp);

    int tail = out_size - (DENSE + MASKN);
    if (tail > 0)
        k_zero_tail<<<(tail + 255)/256, 256>>>(out, DENSE + MASKN, tail);

    int aggBlocks = (NN*32 + 255)/256;
    for (int l = 0; l < NLAYERS - 1; l++) {
        k_agg<<<aggBlocks, 256>>>(py);
        k_gemm_mma<false><<<GEMM_NB, 256>>>(papk, pwpk + l*DD*DD*2, bs + l*DD, py, nullptr, batch);
    }
    k_agg<<<aggBlocks, 256>>>(py);
    k_gemm_mma<true><<<GEMM_NB, 256>>>(papk, pwpk + 4*DD*DD*2, bs + 4*DD, nullptr, out, batch);
}